// round 9
// baseline (speedup 1.0000x reference)
#include <cuda_runtime.h>
#include <cuda_bf16.h>
#include <cstdint>

#define BB   4096
#define OBSD 512
#define ACTD 64
#define NT   10
#define NE   16
#define DREP 1024
#define DH   1024
#define DKK  512
#define XDIM 576   // OBSD+ACTD
#define SDIM 522   // OBSD+NT

// ---------------- scratch (device globals; no allocs allowed) ----------------
__device__ __align__(256) float g_x[BB * XDIM];
__device__ int   g_task[BB];
__device__ float g_wq[NE * NT * DH];
__device__ float g_qb[NE * NT];
__device__ __align__(256) float g_h0[BB * DREP];
__device__ __align__(256) float g_rep[BB * DREP];
__device__ float g_logits[BB * NE];
__device__ float g_attn[BB * NE];
__device__ __align__(256) float g_gv[(size_t)BB * NE * DH];   // attn-scaled hv, [b][e*DH+h]
__device__ __align__(256) float g_tin[BB * DKK];
__device__ __align__(256) float g_t1[BB * 512];
__device__ __align__(256) float g_t2[BB * 256];
__device__ float g_loss;

// ---------------- helpers ----------------
__device__ __forceinline__ float rna_tf32(float x) {
    uint32_t u;
    asm("cvt.rna.tf32.f32 %0, %1;" : "=r"(u) : "f"(x));
    return __uint_as_float(u);
}
__device__ __forceinline__ uint32_t rna_tf32_bits(float x) {
    uint32_t u;
    asm("cvt.rna.tf32.f32 %0, %1;" : "=r"(u) : "f"(x));
    return u;
}

__device__ __forceinline__ void cpa16(void* smem, const void* gsrc) {
    uint32_t sa = (uint32_t)__cvta_generic_to_shared(smem);
    asm volatile("cp.async.cg.shared.global [%0], [%1], 16;\n" :: "r"(sa), "l"(gsrc));
}
__device__ __forceinline__ void cpa_commit() { asm volatile("cp.async.commit_group;\n" ::); }

__device__ __forceinline__ void mma_tf32(float* c, const uint32_t* a, const uint32_t* b) {
    asm volatile(
        "mma.sync.aligned.m16n8k8.row.col.f32.tf32.tf32.f32 "
        "{%0,%1,%2,%3}, {%4,%5,%6,%7}, {%8,%9}, {%0,%1,%2,%3};"
        : "+f"(c[0]), "+f"(c[1]), "+f"(c[2]), "+f"(c[3])
        : "r"(a[0]), "r"(a[1]), "r"(a[2]), "r"(a[3]), "r"(b[0]), "r"(b[1]));
}

// ---------------- small kernels ----------------
__global__ void prep_kernel(const float* __restrict__ state, const float* __restrict__ act) {
    int b = blockIdx.x;
    const float* srow = state + (size_t)b * SDIM;
    float* xrow = g_x + (size_t)b * XDIM;
    for (int i = threadIdx.x; i < XDIM; i += blockDim.x) {
        float v = (i < OBSD) ? srow[i] : act[(size_t)b * ACTD + (i - OBSD)];
        xrow[i] = rna_tf32(v);
    }
    if (threadIdx.x == 0) {
        float best = srow[OBSD]; int bi = 0;
        for (int t = 1; t < NT; t++) { float v = srow[OBSD + t]; if (v > best) { best = v; bi = t; } }
        g_task[b] = bi;
    }
}

// wq[e,t,h] = sum_k Wk1[e,h,k] * tanh(emb[t,k]);  qb[e,t] = sum_k bk1[e,k]*tanh(emb[t,k])
__global__ void wq_kernel(const float* __restrict__ Wk1, const float* __restrict__ bk1,
                          const float* __restrict__ emb) {
    int e = blockIdx.x, t = blockIdx.y;
    __shared__ float q[DKK];
    for (int k = threadIdx.x; k < DKK; k += blockDim.x) q[k] = tanhf(emb[t * DKK + k]);
    __syncthreads();
    const float* Wb = Wk1 + (size_t)e * DH * DKK;
    for (int h = threadIdx.x; h < DH; h += blockDim.x) {
        const float* wr = Wb + (size_t)h * DKK;
        float s = 0.f;
        for (int k = 0; k < DKK; k++) s += wr[k] * q[k];
        g_wq[((size_t)e * NT + t) * DH + h] = s;
    }
    if (threadIdx.x == 0) {
        float s = 0.f;
        const float* br = bk1 + (size_t)e * DKK;
        for (int k = 0; k < DKK; k++) s += br[k] * q[k];
        g_qb[e * NT + t] = s;
    }
}

__global__ void initlogits_kernel() {
    int i = blockIdx.x * blockDim.x + threadIdx.x;
    if (i < BB * NE) {
        int b = i >> 4, e = i & 15;
        g_logits[i] = g_qb[e * NT + g_task[b]];
    }
    if (i == 0) g_loss = 0.f;
}

__global__ void softmax_kernel() {
    int b = blockIdx.x * blockDim.x + threadIdx.x;  // grid exact: BB threads
    float l[NE];
    float mx = -1e30f;
#pragma unroll
    for (int e = 0; e < NE; e++) { l[e] = g_logits[b * NE + e]; mx = fmaxf(mx, l[e]); }
    float s = 0.f;
#pragma unroll
    for (int e = 0; e < NE; e++) { l[e] = expf(l[e] - mx); s += l[e]; }
    float inv = 1.f / s;
    float lp = 0.f;
#pragma unroll
    for (int e = 0; e < NE; e++) {
        float a = l[e] * inv;
        g_attn[b * NE + e] = a;
        float lg = logf(a + 1e-10f);
        lp += fminf(fmaxf(lg, -6.f), 0.f);
    }
#pragma unroll
    for (int o = 16; o > 0; o >>= 1) lp += __shfl_xor_sync(0xffffffffu, lp, o);
    __shared__ float red[8];
    if ((threadIdx.x & 31) == 0) red[threadIdx.x >> 5] = lp;
    __syncthreads();
    if (threadIdx.x == 0) {
        float sb = 0.f;
        for (int w = 0; w < (int)(blockDim.x >> 5); w++) sb += red[w];
        atomicAdd(&g_loss, sb);
    }
}

// tin = round_tf32( tin + sum_e attn[b,e]*bv1[e,k] )
__global__ void mixbias_kernel(const float* __restrict__ bv1) {
    int i = blockIdx.x * blockDim.x + threadIdx.x;
    if (i < BB * DKK) {
        int b = i >> 9, k = i & 511;
        float s = g_tin[i];
#pragma unroll
        for (int e = 0; e < NE; e++) s += g_attn[b * NE + e] * bv1[e * DKK + k];
        g_tin[i] = rna_tf32(s);
    }
}

__global__ void finalize_kernel(const float* __restrict__ Wt2, const float* __restrict__ bt2,
                                float* __restrict__ out, int out_size) {
    int wid = threadIdx.x >> 5, lane = threadIdx.x & 31;
    int b = blockIdx.x * 8 + wid;
    const float* row = g_t2 + (size_t)b * 256;
    float s = 0.f;
#pragma unroll
    for (int k = 0; k < 256; k += 32) s += row[k + lane] * Wt2[k + lane];
#pragma unroll
    for (int o = 16; o > 0; o >>= 1) s += __shfl_xor_sync(0xffffffffu, s, o);
    if (lane == 0) out[b] = s + bt2[0];
    if (blockIdx.x == 0 && threadIdx.x == 0 && out_size > BB)
        out[out_size - 1] = -(0.3f / (float)BB) * g_loss;
}

// ---------------- tf32 tensor-core GEMM (3-stage cp.async pipeline) ----------------
// C(M x N) = epi( A(M x K) @ B(K x N) + bias ). A is tf32-pre-rounded by its
// producer; B is RAW weights, rounded to tf32 in the register fragment path.
// Tile 128x128x16, 8 warps (2x4), warp tile 64x32, mma m16n8k8.
// 3 smem stages, ONE __syncthreads per k-tile, depth-2 prefetch.
// EPI: 0 raw store, 1 relu+round, 2 round, 3 fused-logit (no C), 4 relu*attn+round, 5 relu
#define BM 128
#define BN 128
#define BKT 16
#define ASTR (BKT + 4)   // 20: conflict-free A-frag loads
#define BSTR (BN + 8)    // 136: conflict-free B-frag loads
#define NSTG 3
#define SMEM3_BYTES ((NSTG * BM * ASTR + NSTG * BKT * BSTR) * 4)

template <int EPI>
__global__ void __launch_bounds__(256) gemm_tf32(
    const float* __restrict__ A, int lda,
    const float* __restrict__ B, int ldb, long long sB,
    float* __restrict__ C, int ldc, long long sC,
    const float* __restrict__ bias, int sBias,
    int K)
{
    extern __shared__ float sm[];
    float* Asb = sm;                          // [NSTG][BM][ASTR]
    float* Bsb = sm + NSTG * BM * ASTR;       // [NSTG][BKT][BSTR]

    const int e = blockIdx.z;
    const float* Bp = B + (size_t)e * (size_t)sB;
    const float* biasp = bias ? bias + (size_t)e * (size_t)sBias : nullptr;
    const int bm0 = blockIdx.y * BM, bn0 = blockIdx.x * BN;
    const int tid = threadIdx.x;
    const int wid = tid >> 5, lane = tid & 31;
    const int wm = wid >> 2, wn = wid & 3;  // 2 x 4 warp grid
    const int g = lane >> 2, t = lane & 3;

    const int am = tid >> 2, akq = tid & 3;   // A stage: rows am, am+64; quad akq
    const int bk = tid >> 5, bnq = tid & 31;  // B stage: rows bk, bk+8; quad bnq

    const int nk = K / BKT;

    auto loadStage = [&](int s, int kt) {
        int k0 = kt * BKT;
        float* As = Asb + s * BM * ASTR;
        float* Bst = Bsb + s * BKT * BSTR;
        cpa16(&As[am * ASTR + akq * 4],        A + (size_t)(bm0 + am) * lda + k0 + akq * 4);
        cpa16(&As[(am + 64) * ASTR + akq * 4], A + (size_t)(bm0 + am + 64) * lda + k0 + akq * 4);
        cpa16(&Bst[bk * BSTR + bnq * 4],       Bp + (size_t)(k0 + bk) * ldb + bn0 + bnq * 4);
        cpa16(&Bst[(bk + 8) * BSTR + bnq * 4], Bp + (size_t)(k0 + bk + 8) * ldb + bn0 + bnq * 4);
        cpa_commit();
    };

    float acc[4][4][4];
#pragma unroll
    for (int a = 0; a < 4; a++)
#pragma unroll
        for (int b2 = 0; b2 < 4; b2++)
#pragma unroll
            for (int c2 = 0; c2 < 4; c2++) acc[a][b2][c2] = 0.f;

    // prologue: stages 0 and 1 in flight
    loadStage(0, 0);
    loadStage(1, 1);

    for (int kt = 0; kt < nk; ++kt) {
        // stage kt must be resident. Groups complete in order, so:
        //  - while more groups are outstanding, allow 1 pending (group kt+1)
        //  - on the last iteration everything must drain
        if (kt + 1 < nk) { asm volatile("cp.async.wait_group 1;\n" ::); }
        else             { asm volatile("cp.async.wait_group 0;\n" ::); }
        __syncthreads();   // all threads see stage kt; stage (kt+2)%3 fully consumed

        if (kt + 2 < nk) loadStage((kt + 2) % NSTG, kt + 2);

        const float* As = Asb + (kt % NSTG) * BM * ASTR;
        const float* Bst = Bsb + (kt % NSTG) * BKT * BSTR;
#pragma unroll
        for (int sub = 0; sub < 2; ++sub) {
            int kb = sub * 8;
            uint32_t af[4][4], bf[4][2];
#pragma unroll
            for (int mi = 0; mi < 4; mi++) {
                int r = wm * 64 + mi * 16 + g;
                af[mi][0] = __float_as_uint(As[r * ASTR + kb + t]);
                af[mi][1] = __float_as_uint(As[(r + 8) * ASTR + kb + t]);
                af[mi][2] = __float_as_uint(As[r * ASTR + kb + t + 4]);
                af[mi][3] = __float_as_uint(As[(r + 8) * ASTR + kb + t + 4]);
            }
#pragma unroll
            for (int ni = 0; ni < 4; ni++) {
                int c = wn * 32 + ni * 8 + g;
                bf[ni][0] = rna_tf32_bits(Bst[(kb + t) * BSTR + c]);
                bf[ni][1] = rna_tf32_bits(Bst[(kb + t + 4) * BSTR + c]);
            }
#pragma unroll
            for (int mi = 0; mi < 4; mi++)
#pragma unroll
                for (int ni = 0; ni < 4; ni++)
                    mma_tf32(acc[mi][ni], af[mi], bf[ni]);
        }
    }

    const int roff = bm0 + wm * 64;
    const int coff = bn0 + wn * 32;

    if (EPI == 3) {
        // logits[b,e] += sum_cols relu(acc+bias) * wq[e, task[b], col]
        float rs[4][2];
#pragma unroll
        for (int mi = 0; mi < 4; mi++) { rs[mi][0] = 0.f; rs[mi][1] = 0.f; }
#pragma unroll
        for (int mi = 0; mi < 4; mi++) {
            int r0 = roff + mi * 16 + g, r1 = r0 + 8;
            const float* w0 = g_wq + ((size_t)e * NT + g_task[r0]) * DH;
            const float* w1 = g_wq + ((size_t)e * NT + g_task[r1]) * DH;
#pragma unroll
            for (int ni = 0; ni < 4; ni++) {
                int c0 = coff + ni * 8 + 2 * t;
                float b0v = biasp[c0], b1v = biasp[c0 + 1];
                rs[mi][0] += fmaxf(acc[mi][ni][0] + b0v, 0.f) * w0[c0];
                rs[mi][0] += fmaxf(acc[mi][ni][1] + b1v, 0.f) * w0[c0 + 1];
                rs[mi][1] += fmaxf(acc[mi][ni][2] + b0v, 0.f) * w1[c0];
                rs[mi][1] += fmaxf(acc[mi][ni][3] + b1v, 0.f) * w1[c0 + 1];
            }
        }
#pragma unroll
        for (int mi = 0; mi < 4; mi++)
#pragma unroll
            for (int h = 0; h < 2; h++) {
                rs[mi][h] += __shfl_xor_sync(0xffffffffu, rs[mi][h], 1);
                rs[mi][h] += __shfl_xor_sync(0xffffffffu, rs[mi][h], 2);
            }
        if (t == 0) {
#pragma unroll
            for (int mi = 0; mi < 4; mi++) {
                int r0 = roff + mi * 16 + g;
                atomicAdd(&g_logits[(size_t)r0 * NE + e], rs[mi][0]);
                atomicAdd(&g_logits[(size_t)(r0 + 8) * NE + e], rs[mi][1]);
            }
        }
    } else {
        float* Cp = C + (size_t)e * (size_t)sC;
#pragma unroll
        for (int mi = 0; mi < 4; mi++) {
            int r0 = roff + mi * 16 + g, r1 = r0 + 8;
            float s0 = 1.f, s1 = 1.f;
            if (EPI == 4) { s0 = g_attn[(size_t)r0 * NE + e]; s1 = g_attn[(size_t)r1 * NE + e]; }
#pragma unroll
            for (int ni = 0; ni < 4; ni++) {
                int c0 = coff + ni * 8 + 2 * t;
                float bb0 = biasp ? biasp[c0] : 0.f;
                float bb1 = biasp ? biasp[c0 + 1] : 0.f;
                float v00 = acc[mi][ni][0] + bb0, v01 = acc[mi][ni][1] + bb1;
                float v10 = acc[mi][ni][2] + bb0, v11 = acc[mi][ni][3] + bb1;
                if (EPI == 1 || EPI == 4 || EPI == 5) {
                    v00 = fmaxf(v00, 0.f); v01 = fmaxf(v01, 0.f);
                    v10 = fmaxf(v10, 0.f); v11 = fmaxf(v11, 0.f);
                }
                if (EPI == 4) { v00 *= s0; v01 *= s0; v10 *= s1; v11 *= s1; }
                if (EPI == 1 || EPI == 2 || EPI == 4) {
                    v00 = rna_tf32(v00); v01 = rna_tf32(v01);
                    v10 = rna_tf32(v10); v11 = rna_tf32(v11);
                }
                Cp[(size_t)r0 * ldc + c0] = v00; Cp[(size_t)r0 * ldc + c0 + 1] = v01;
                Cp[(size_t)r1 * ldc + c0] = v10; Cp[(size_t)r1 * ldc + c0 + 1] = v11;
            }
        }
    }
}

// ---------------- launch ----------------
extern "C" void kernel_launch(void* const* d_in, const int* in_sizes, int n_in,
                              void* d_out, int out_size) {
    const float* state = (const float*)d_in[0];
    const float* act   = (const float*)d_in[1];
    const float* repW0 = (const float*)d_in[2];
    const float* repb0 = (const float*)d_in[3];
    const float* repW1 = (const float*)d_in[4];
    const float* repb1 = (const float*)d_in[5];
    const float* emb   = (const float*)d_in[6];
    const float* Wk0   = (const float*)d_in[7];
    const float* bk0   = (const float*)d_in[8];
    const float* Wk1   = (const float*)d_in[9];
    const float* bk1   = (const float*)d_in[10];
    const float* Wv0   = (const float*)d_in[11];
    const float* bv0   = (const float*)d_in[12];
    const float* Wv1   = (const float*)d_in[13];
    const float* bv1   = (const float*)d_in[14];
    const float* Wt0   = (const float*)d_in[15];
    const float* bt0   = (const float*)d_in[16];
    const float* Wt1   = (const float*)d_in[17];
    const float* bt1   = (const float*)d_in[18];
    const float* Wt2   = (const float*)d_in[19];
    const float* bt2   = (const float*)d_in[20];
    (void)in_sizes; (void)n_in;

    // allow >48KB dynamic smem on all GEMM instantiations (host-side, capture-safe)
    cudaFuncSetAttribute((const void*)gemm_tf32<0>, cudaFuncAttributeMaxDynamicSharedMemorySize, SMEM3_BYTES);
    cudaFuncSetAttribute((const void*)gemm_tf32<1>, cudaFuncAttributeMaxDynamicSharedMemorySize, SMEM3_BYTES);
    cudaFuncSetAttribute((const void*)gemm_tf32<2>, cudaFuncAttributeMaxDynamicSharedMemorySize, SMEM3_BYTES);
    cudaFuncSetAttribute((const void*)gemm_tf32<3>, cudaFuncAttributeMaxDynamicSharedMemorySize, SMEM3_BYTES);
    cudaFuncSetAttribute((const void*)gemm_tf32<4>, cudaFuncAttributeMaxDynamicSharedMemorySize, SMEM3_BYTES);
    cudaFuncSetAttribute((const void*)gemm_tf32<5>, cudaFuncAttributeMaxDynamicSharedMemorySize, SMEM3_BYTES);

    float *xp, *h0p, *repp, *gvp, *tinp, *t1p, *t2p;
    cudaGetSymbolAddress((void**)&xp, g_x);
    cudaGetSymbolAddress((void**)&h0p, g_h0);
    cudaGetSymbolAddress((void**)&repp, g_rep);
    cudaGetSymbolAddress((void**)&gvp, g_gv);
    cudaGetSymbolAddress((void**)&tinp, g_tin);
    cudaGetSymbolAddress((void**)&t1p, g_t1);
    cudaGetSymbolAddress((void**)&t2p, g_t2);

    prep_kernel<<<BB, 128>>>(state, act);
    wq_kernel<<<dim3(NE, NT), 256>>>(Wk1, bk1, emb);
    initlogits_kernel<<<(BB * NE) / 256, 256>>>();

    // h0 = relu(x @ W0 + b0)
    gemm_tf32<1><<<dim3(DREP / BN, BB / BM, 1), 256, SMEM3_BYTES>>>(
        xp, XDIM, repW0, DREP, 0, h0p, DREP, 0, repb0, 0, XDIM);
    // rep = h0 @ W1 + b1   (rounded)
    gemm_tf32<2><<<dim3(DREP / BN, BB / BM, 1), 256, SMEM3_BYTES>>>(
        h0p, DREP, repW1, DREP, 0, repp, DREP, 0, repb1, 0, DREP);
    // fused: logits += relu(rep @ Wk0[e] + bk0[e]) . wq[e,task,:]   (batched z=16)
    gemm_tf32<3><<<dim3(DH / BN, BB / BM, NE), 256, SMEM3_BYTES>>>(
        repp, DREP, Wk0, DH, (long long)DREP * DH, nullptr, 0, 0, bk0, DH, DREP);

    softmax_kernel<<<BB / 256, 256>>>();

    // gv[b][e*DH+h] = attn[b,e] * relu(rep @ Wv0[e] + bv0[e])
    gemm_tf32<4><<<dim3(DH / BN, BB / BM, NE), 256, SMEM3_BYTES>>>(
        repp, DREP, Wv0, DH, (long long)DREP * DH, gvp, NE * DH, DH, bv0, DH, DREP);
    // tower_in = gv @ Wv1_flat  (K = 16384)
    gemm_tf32<0><<<dim3(DKK / BN, BB / BM, 1), 256, SMEM3_BYTES>>>(
        gvp, NE * DH, Wv1, DKK, 0, tinp, DKK, 0, nullptr, 0, NE * DH);
    mixbias_kernel<<<(BB * DKK) / 256, 256>>>(bv1);

    // tower
    gemm_tf32<1><<<dim3(512 / BN, BB / BM, 1), 256, SMEM3_BYTES>>>(
        tinp, DKK, Wt0, 512, 0, t1p, 512, 0, bt0, 0, DKK);
    gemm_tf32<5><<<dim3(256 / BN, BB / BM, 1), 256, SMEM3_BYTES>>>(
        t1p, 512, Wt1, 256, 0, t2p, 256, 0, bt1, 0, 512);

    finalize_kernel<<<BB / 8, 256>>>(Wt2, bt2, (float*)d_out, out_size);
}

// round 16
// speedup vs baseline: 1.0096x; 1.0096x over previous
#include <cuda_runtime.h>
#include <cuda_bf16.h>
#include <cstdint>

#define BB   4096
#define OBSD 512
#define ACTD 64
#define NT   10
#define NE   16
#define DREP 1024
#define DH   1024
#define DKK  512
#define XDIM 576   // OBSD+ACTD
#define SDIM 522   // OBSD+NT

// ---------------- scratch (device globals; no allocs allowed) ----------------
__device__ __align__(256) float g_x[BB * XDIM];
__device__ int   g_task[BB];
__device__ float g_wq[NE * NT * DH];
__device__ float g_qb[NE * NT];
__device__ __align__(256) float g_h0[BB * DREP];
__device__ __align__(256) float g_rep[BB * DREP];
__device__ float g_logits[BB * NE];
__device__ float g_attn[BB * NE];
__device__ __align__(256) float g_gv[(size_t)BB * NE * DH];   // attn-scaled hv, [b][e*DH+h]
__device__ __align__(256) float g_tin[BB * DKK];
__device__ __align__(256) float g_t1[BB * 512];
__device__ __align__(256) float g_t2[BB * 256];
__device__ float g_loss;

// ---------------- helpers ----------------
__device__ __forceinline__ float rna_tf32(float x) {
    uint32_t u;
    asm("cvt.rna.tf32.f32 %0, %1;" : "=r"(u) : "f"(x));
    return __uint_as_float(u);
}
__device__ __forceinline__ uint32_t rna_tf32_bits(float x) {
    uint32_t u;
    asm("cvt.rna.tf32.f32 %0, %1;" : "=r"(u) : "f"(x));
    return u;
}

__device__ __forceinline__ void cpa16(void* smem, const void* gsrc) {
    uint32_t sa = (uint32_t)__cvta_generic_to_shared(smem);
    asm volatile("cp.async.cg.shared.global [%0], [%1], 16;\n" :: "r"(sa), "l"(gsrc));
}
__device__ __forceinline__ void cpa_commit() { asm volatile("cp.async.commit_group;\n" ::); }

__device__ __forceinline__ void mma_tf32(float* c, const uint32_t* a, const uint32_t* b) {
    asm volatile(
        "mma.sync.aligned.m16n8k8.row.col.f32.tf32.tf32.f32 "
        "{%0,%1,%2,%3}, {%4,%5,%6,%7}, {%8,%9}, {%0,%1,%2,%3};"
        : "+f"(c[0]), "+f"(c[1]), "+f"(c[2]), "+f"(c[3])
        : "r"(a[0]), "r"(a[1]), "r"(a[2]), "r"(a[3]), "r"(b[0]), "r"(b[1]));
}

// ---------------- small kernels ----------------
__global__ void prep_kernel(const float* __restrict__ state, const float* __restrict__ act) {
    int b = blockIdx.x;
    const float* srow = state + (size_t)b * SDIM;
    float* xrow = g_x + (size_t)b * XDIM;
    for (int i = threadIdx.x; i < XDIM; i += blockDim.x) {
        float v = (i < OBSD) ? srow[i] : act[(size_t)b * ACTD + (i - OBSD)];
        xrow[i] = rna_tf32(v);
    }
    if (threadIdx.x == 0) {
        float best = srow[OBSD]; int bi = 0;
        for (int t = 1; t < NT; t++) { float v = srow[OBSD + t]; if (v > best) { best = v; bi = t; } }
        g_task[b] = bi;
    }
}

// wq[e,t,h] = sum_k Wk1[e,h,k] * tanh(emb[t,k]);  qb[e,t] = sum_k bk1[e,k]*tanh(emb[t,k])
__global__ void wq_kernel(const float* __restrict__ Wk1, const float* __restrict__ bk1,
                          const float* __restrict__ emb) {
    int e = blockIdx.x, t = blockIdx.y;
    __shared__ float q[DKK];
    for (int k = threadIdx.x; k < DKK; k += blockDim.x) q[k] = tanhf(emb[t * DKK + k]);
    __syncthreads();
    const float* Wb = Wk1 + (size_t)e * DH * DKK;
    for (int h = threadIdx.x; h < DH; h += blockDim.x) {
        const float* wr = Wb + (size_t)h * DKK;
        float s = 0.f;
        for (int k = 0; k < DKK; k++) s += wr[k] * q[k];
        g_wq[((size_t)e * NT + t) * DH + h] = s;
    }
    if (threadIdx.x == 0) {
        float s = 0.f;
        const float* br = bk1 + (size_t)e * DKK;
        for (int k = 0; k < DKK; k++) s += br[k] * q[k];
        g_qb[e * NT + t] = s;
    }
}

__global__ void initlogits_kernel() {
    int i = blockIdx.x * blockDim.x + threadIdx.x;
    if (i < BB * NE) {
        int b = i >> 4, e = i & 15;
        g_logits[i] = g_qb[e * NT + g_task[b]];
    }
    if (i == 0) g_loss = 0.f;
}

__global__ void softmax_kernel() {
    int b = blockIdx.x * blockDim.x + threadIdx.x;  // grid exact: BB threads
    float l[NE];
    float mx = -1e30f;
#pragma unroll
    for (int e = 0; e < NE; e++) { l[e] = g_logits[b * NE + e]; mx = fmaxf(mx, l[e]); }
    float s = 0.f;
#pragma unroll
    for (int e = 0; e < NE; e++) { l[e] = expf(l[e] - mx); s += l[e]; }
    float inv = 1.f / s;
    float lp = 0.f;
#pragma unroll
    for (int e = 0; e < NE; e++) {
        float a = l[e] * inv;
        g_attn[b * NE + e] = a;
        float lg = logf(a + 1e-10f);
        lp += fminf(fmaxf(lg, -6.f), 0.f);
    }
#pragma unroll
    for (int o = 16; o > 0; o >>= 1) lp += __shfl_xor_sync(0xffffffffu, lp, o);
    __shared__ float red[8];
    if ((threadIdx.x & 31) == 0) red[threadIdx.x >> 5] = lp;
    __syncthreads();
    if (threadIdx.x == 0) {
        float sb = 0.f;
        for (int w = 0; w < (int)(blockDim.x >> 5); w++) sb += red[w];
        atomicAdd(&g_loss, sb);
    }
}

// tin = round_tf32( tin + sum_e attn[b,e]*bv1[e,k] )
__global__ void mixbias_kernel(const float* __restrict__ bv1) {
    int i = blockIdx.x * blockDim.x + threadIdx.x;
    if (i < BB * DKK) {
        int b = i >> 9, k = i & 511;
        float s = g_tin[i];
#pragma unroll
        for (int e = 0; e < NE; e++) s += g_attn[b * NE + e] * bv1[e * DKK + k];
        g_tin[i] = rna_tf32(s);
    }
}

__global__ void finalize_kernel(const float* __restrict__ Wt2, const float* __restrict__ bt2,
                                float* __restrict__ out, int out_size) {
    int wid = threadIdx.x >> 5, lane = threadIdx.x & 31;
    int b = blockIdx.x * 8 + wid;
    const float* row = g_t2 + (size_t)b * 256;
    float s = 0.f;
#pragma unroll
    for (int k = 0; k < 256; k += 32) s += row[k + lane] * Wt2[k + lane];
#pragma unroll
    for (int o = 16; o > 0; o >>= 1) s += __shfl_xor_sync(0xffffffffu, s, o);
    if (lane == 0) out[b] = s + bt2[0];
    if (blockIdx.x == 0 && threadIdx.x == 0 && out_size > BB)
        out[out_size - 1] = -(0.3f / (float)BB) * g_loss;
}

// ---------------- tf32 tensor-core GEMM ----------------
// C(M x N) = epi( A(M x K) @ B(K x N) + bias ). A pre-rounded tf32 by producer;
// B raw weights, rounded in the register fragment path.
// Block 128x128x16, 4 warps (2x2 grid), warp tile 64x64, mma m16n8k8.
// High-ILP re-tiling: 32 acc tiles/warp; A/B fragments each shared by only 2 warps.
// EPI: 0 raw store, 1 relu+round, 2 round, 3 fused-logit (no C), 4 relu*attn+round, 5 relu
#define BM 128
#define BN 128
#define BKT 16
#define ASTR (BKT + 4)   // 20: conflict-free A-frag loads
#define BSTR (BN + 8)    // 136: conflict-free B-frag loads

template <int EPI>
__global__ void __launch_bounds__(128) gemm_tf32(
    const float* __restrict__ A, int lda,
    const float* __restrict__ B, int ldb, long long sB,
    float* __restrict__ C, int ldc, long long sC,
    const float* __restrict__ bias, int sBias,
    int K)
{
    __shared__ float As[2][BM][ASTR];
    __shared__ float Bs[2][BKT][BSTR];

    const int e = blockIdx.z;
    const float* Bp = B + (size_t)e * (size_t)sB;
    const float* biasp = bias ? bias + (size_t)e * (size_t)sBias : nullptr;
    const int bm0 = blockIdx.y * BM, bn0 = blockIdx.x * BN;
    const int tid = threadIdx.x;
    const int wid = tid >> 5, lane = tid & 31;
    const int wm = wid >> 1, wn = wid & 1;   // 2 x 2 warp grid, 64x64 warp tile
    const int g = lane >> 2, t = lane & 3;

    const int nk = K / BKT;

    // staging: 512 x 16B for A (128 rows x 4 quads), 512 x 16B for B (16 rows x 32 quads)
    auto loadStage = [&](int s, int kt) {
        int k0 = kt * BKT;
#pragma unroll
        for (int i = 0; i < 4; i++) {
            int idx = tid + i * 128;
            int ar = idx >> 2, aq = idx & 3;
            cpa16(&As[s][ar][aq * 4], A + (size_t)(bm0 + ar) * lda + k0 + aq * 4);
            int br = idx >> 5, bq = idx & 31;
            cpa16(&Bs[s][br][bq * 4], Bp + (size_t)(k0 + br) * ldb + bn0 + bq * 4);
        }
        cpa_commit();
    };

    float acc[4][8][4];
#pragma unroll
    for (int a = 0; a < 4; a++)
#pragma unroll
        for (int b2 = 0; b2 < 8; b2++)
#pragma unroll
            for (int c2 = 0; c2 < 4; c2++) acc[a][b2][c2] = 0.f;

    loadStage(0, 0);
    if (nk > 1) {
        loadStage(1, 1);
        asm volatile("cp.async.wait_group 1;\n" ::);
    } else {
        asm volatile("cp.async.wait_group 0;\n" ::);
    }
    __syncthreads();

    for (int kt = 0; kt < nk; ++kt) {
        int cur = kt & 1;
#pragma unroll
        for (int sub = 0; sub < 2; ++sub) {
            int kb = sub * 8;
            uint32_t af[4][4], bf[8][2];
#pragma unroll
            for (int mi = 0; mi < 4; mi++) {
                int r = wm * 64 + mi * 16 + g;
                af[mi][0] = __float_as_uint(As[cur][r][kb + t]);
                af[mi][1] = __float_as_uint(As[cur][r + 8][kb + t]);
                af[mi][2] = __float_as_uint(As[cur][r][kb + t + 4]);
                af[mi][3] = __float_as_uint(As[cur][r + 8][kb + t + 4]);
            }
#pragma unroll
            for (int ni = 0; ni < 8; ni++) {
                int c = wn * 64 + ni * 8 + g;
                bf[ni][0] = rna_tf32_bits(Bs[cur][kb + t][c]);
                bf[ni][1] = rna_tf32_bits(Bs[cur][kb + t + 4][c]);
            }
#pragma unroll
            for (int mi = 0; mi < 4; mi++)
#pragma unroll
                for (int ni = 0; ni < 8; ni++)
                    mma_tf32(acc[mi][ni], af[mi], bf[ni]);
        }
        __syncthreads();
        if (kt + 2 < nk) loadStage(cur, kt + 2);
        if (kt + 1 < nk) {
            if (kt + 2 < nk) { asm volatile("cp.async.wait_group 1;\n" ::); }
            else             { asm volatile("cp.async.wait_group 0;\n" ::); }
            __syncthreads();
        }
    }

    const int roff = bm0 + wm * 64;
    const int coff = bn0 + wn * 64;

    if (EPI == 3) {
        // logits[b,e] += sum_cols relu(acc+bias) * wq[e, task[b], col]
        float rs[4][2];
#pragma unroll
        for (int mi = 0; mi < 4; mi++) { rs[mi][0] = 0.f; rs[mi][1] = 0.f; }
#pragma unroll
        for (int mi = 0; mi < 4; mi++) {
            int r0 = roff + mi * 16 + g, r1 = r0 + 8;
            const float* w0 = g_wq + ((size_t)e * NT + g_task[r0]) * DH;
            const float* w1 = g_wq + ((size_t)e * NT + g_task[r1]) * DH;
#pragma unroll
            for (int ni = 0; ni < 8; ni++) {
                int c0 = coff + ni * 8 + 2 * t;
                float b0v = biasp[c0], b1v = biasp[c0 + 1];
                rs[mi][0] += fmaxf(acc[mi][ni][0] + b0v, 0.f) * w0[c0];
                rs[mi][0] += fmaxf(acc[mi][ni][1] + b1v, 0.f) * w0[c0 + 1];
                rs[mi][1] += fmaxf(acc[mi][ni][2] + b0v, 0.f) * w1[c0];
                rs[mi][1] += fmaxf(acc[mi][ni][3] + b1v, 0.f) * w1[c0 + 1];
            }
        }
#pragma unroll
        for (int mi = 0; mi < 4; mi++)
#pragma unroll
            for (int h = 0; h < 2; h++) {
                rs[mi][h] += __shfl_xor_sync(0xffffffffu, rs[mi][h], 1);
                rs[mi][h] += __shfl_xor_sync(0xffffffffu, rs[mi][h], 2);
            }
        if (t == 0) {
#pragma unroll
            for (int mi = 0; mi < 4; mi++) {
                int r0 = roff + mi * 16 + g;
                atomicAdd(&g_logits[(size_t)r0 * NE + e], rs[mi][0]);
                atomicAdd(&g_logits[(size_t)(r0 + 8) * NE + e], rs[mi][1]);
            }
        }
    } else {
        float* Cp = C + (size_t)e * (size_t)sC;
#pragma unroll
        for (int mi = 0; mi < 4; mi++) {
            int r0 = roff + mi * 16 + g, r1 = r0 + 8;
            float s0 = 1.f, s1 = 1.f;
            if (EPI == 4) { s0 = g_attn[(size_t)r0 * NE + e]; s1 = g_attn[(size_t)r1 * NE + e]; }
#pragma unroll
            for (int ni = 0; ni < 8; ni++) {
                int c0 = coff + ni * 8 + 2 * t;
                float bb0 = biasp ? biasp[c0] : 0.f;
                float bb1 = biasp ? biasp[c0 + 1] : 0.f;
                float v00 = acc[mi][ni][0] + bb0, v01 = acc[mi][ni][1] + bb1;
                float v10 = acc[mi][ni][2] + bb0, v11 = acc[mi][ni][3] + bb1;
                if (EPI == 1 || EPI == 4 || EPI == 5) {
                    v00 = fmaxf(v00, 0.f); v01 = fmaxf(v01, 0.f);
                    v10 = fmaxf(v10, 0.f); v11 = fmaxf(v11, 0.f);
                }
                if (EPI == 4) { v00 *= s0; v01 *= s0; v10 *= s1; v11 *= s1; }
                if (EPI == 1 || EPI == 2 || EPI == 4) {
                    v00 = rna_tf32(v00); v01 = rna_tf32(v01);
                    v10 = rna_tf32(v10); v11 = rna_tf32(v11);
                }
                Cp[(size_t)r0 * ldc + c0] = v00; Cp[(size_t)r0 * ldc + c0 + 1] = v01;
                Cp[(size_t)r1 * ldc + c0] = v10; Cp[(size_t)r1 * ldc + c0 + 1] = v11;
            }
        }
    }
}

// ---------------- launch ----------------
extern "C" void kernel_launch(void* const* d_in, const int* in_sizes, int n_in,
                              void* d_out, int out_size) {
    const float* state = (const float*)d_in[0];
    const float* act   = (const float*)d_in[1];
    const float* repW0 = (const float*)d_in[2];
    const float* repb0 = (const float*)d_in[3];
    const float* repW1 = (const float*)d_in[4];
    const float* repb1 = (const float*)d_in[5];
    const float* emb   = (const float*)d_in[6];
    const float* Wk0   = (const float*)d_in[7];
    const float* bk0   = (const float*)d_in[8];
    const float* Wk1   = (const float*)d_in[9];
    const float* bk1   = (const float*)d_in[10];
    const float* Wv0   = (const float*)d_in[11];
    const float* bv0   = (const float*)d_in[12];
    const float* Wv1   = (const float*)d_in[13];
    const float* bv1   = (const float*)d_in[14];
    const float* Wt0   = (const float*)d_in[15];
    const float* bt0   = (const float*)d_in[16];
    const float* Wt1   = (const float*)d_in[17];
    const float* bt1   = (const float*)d_in[18];
    const float* Wt2   = (const float*)d_in[19];
    const float* bt2   = (const float*)d_in[20];
    (void)in_sizes; (void)n_in;

    float *xp, *h0p, *repp, *gvp, *tinp, *t1p, *t2p;
    cudaGetSymbolAddress((void**)&xp, g_x);
    cudaGetSymbolAddress((void**)&h0p, g_h0);
    cudaGetSymbolAddress((void**)&repp, g_rep);
    cudaGetSymbolAddress((void**)&gvp, g_gv);
    cudaGetSymbolAddress((void**)&tinp, g_tin);
    cudaGetSymbolAddress((void**)&t1p, g_t1);
    cudaGetSymbolAddress((void**)&t2p, g_t2);

    prep_kernel<<<BB, 128>>>(state, act);
    wq_kernel<<<dim3(NE, NT), 256>>>(Wk1, bk1, emb);
    initlogits_kernel<<<(BB * NE) / 256, 256>>>();

    // h0 = relu(x @ W0 + b0)
    gemm_tf32<1><<<dim3(DREP / BN, BB / BM, 1), 128>>>(
        xp, XDIM, repW0, DREP, 0, h0p, DREP, 0, repb0, 0, XDIM);
    // rep = round(h0 @ W1 + b1)
    gemm_tf32<2><<<dim3(DREP / BN, BB / BM, 1), 128>>>(
        h0p, DREP, repW1, DREP, 0, repp, DREP, 0, repb1, 0, DREP);
    // fused: logits += relu(rep @ Wk0[e] + bk0[e]) . wq[e,task,:]   (batched z=16)
    gemm_tf32<3><<<dim3(DH / BN, BB / BM, NE), 128>>>(
        repp, DREP, Wk0, DH, (long long)DREP * DH, nullptr, 0, 0, bk0, DH, DREP);

    softmax_kernel<<<BB / 256, 256>>>();

    // gv[b][e*DH+h] = attn[b,e] * relu(rep @ Wv0[e] + bv0[e])
    gemm_tf32<4><<<dim3(DH / BN, BB / BM, NE), 128>>>(
        repp, DREP, Wv0, DH, (long long)DREP * DH, gvp, NE * DH, DH, bv0, DH, DREP);
    // tower_in = gv @ Wv1_flat  (K = 16384)
    gemm_tf32<0><<<dim3(DKK / BN, BB / BM, 1), 128>>>(
        gvp, NE * DH, Wv1, DKK, 0, tinp, DKK, 0, nullptr, 0, NE * DH);
    mixbias_kernel<<<(BB * DKK) / 256, 256>>>(bv1);

    // tower
    gemm_tf32<1><<<dim3(512 / BN, BB / BM, 1), 128>>>(
        tinp, DKK, Wt0, 512, 0, t1p, 512, 0, bt0, 0, DKK);
    gemm_tf32<5><<<dim3(256 / BN, BB / BM, 1), 128>>>(
        t1p, 512, Wt1, 256, 0, t2p, 256, 0, bt1, 0, 512);

    finalize_kernel<<<BB / 8, 256>>>(Wt2, bt2, (float*)d_out, out_size);
}

// round 17
// speedup vs baseline: 1.4430x; 1.4294x over previous
#include <cuda_runtime.h>
#include <cuda_fp16.h>
#include <cstdint>

#define BB   4096
#define OBSD 512
#define ACTD 64
#define NT   10
#define NE   16
#define DREP 1024
#define DH   1024
#define DKK  512
#define XDIM 576   // OBSD+ACTD
#define SDIM 522   // OBSD+NT

// ---------------- scratch (device globals; no allocs allowed) ----------------
__device__ __align__(256) __half g_x16[BB * XDIM];
__device__ int   g_task[BB];
__device__ float g_wq[NE * NT * DH];
__device__ float g_qb[NE * NT];
__device__ __align__(256) __half g_h016[BB * DREP];
__device__ __align__(256) __half g_rep16[BB * DREP];
__device__ float g_logits[BB * NE];
__device__ float g_attn[BB * NE];
__device__ __align__(256) __half g_gv16[(size_t)BB * NE * DH];
__device__ __align__(256) float g_tin[BB * DKK];
__device__ __align__(256) __half g_tin16[BB * DKK];
__device__ __align__(256) __half g_t116[BB * 512];
__device__ __align__(256) float g_t2[BB * 256];
__device__ float g_loss;
// packed fp16 weights: P[k/2][n] = (W[2k2][n], W[2k2+1][n])
__device__ __align__(256) __half2 g_pW0[(XDIM / 2) * DREP];
__device__ __align__(256) __half2 g_pW1[(DREP / 2) * DREP];
__device__ __align__(256) __half2 g_pWk0[(size_t)NE * (DREP / 2) * DH];
__device__ __align__(256) __half2 g_pWv0[(size_t)NE * (DREP / 2) * DH];
__device__ __align__(256) __half2 g_pWv1[(size_t)(NE * DH / 2) * DKK];
__device__ __align__(256) __half2 g_pWt0[(DKK / 2) * 512];
__device__ __align__(256) __half2 g_pWt1[(512 / 2) * 256];

// ---------------- helpers ----------------
__device__ __forceinline__ void cpa16(void* smem, const void* gsrc) {
    uint32_t sa = (uint32_t)__cvta_generic_to_shared(smem);
    asm volatile("cp.async.cg.shared.global [%0], [%1], 16;\n" :: "r"(sa), "l"(gsrc));
}
__device__ __forceinline__ void cpa_commit() { asm volatile("cp.async.commit_group;\n" ::); }

__device__ __forceinline__ void mma_f16(float* c, const uint32_t* a, const uint32_t* b) {
    asm volatile(
        "mma.sync.aligned.m16n8k16.row.col.f32.f16.f16.f32 "
        "{%0,%1,%2,%3}, {%4,%5,%6,%7}, {%8,%9}, {%0,%1,%2,%3};"
        : "+f"(c[0]), "+f"(c[1]), "+f"(c[2]), "+f"(c[3])
        : "r"(a[0]), "r"(a[1]), "r"(a[2]), "r"(a[3]), "r"(b[0]), "r"(b[1]));
}

// ---------------- small kernels ----------------
// pack fp32 weight [2*K2][N] -> half2 [K2][N], pair along K
__global__ void pack_kernel(const float* __restrict__ W, __half2* __restrict__ P,
                            int K2, int N) {
    int nq4 = N >> 2;
    int idx = blockIdx.x * blockDim.x + threadIdx.x;
    if (idx < K2 * nq4) {
        int k2 = idx / nq4, nq = idx - k2 * nq4;
        int n = nq * 4;
        float4 lo = *(const float4*)(W + (size_t)(2 * k2) * N + n);
        float4 hi = *(const float4*)(W + (size_t)(2 * k2 + 1) * N + n);
        __half2 o[4] = { __floats2half2_rn(lo.x, hi.x), __floats2half2_rn(lo.y, hi.y),
                         __floats2half2_rn(lo.z, hi.z), __floats2half2_rn(lo.w, hi.w) };
        *(float4*)(P + (size_t)k2 * N + n) = *(float4*)o;
    }
}

__global__ void prep_kernel(const float* __restrict__ state, const float* __restrict__ act) {
    int b = blockIdx.x;
    const float* srow = state + (size_t)b * SDIM;
    __half* xrow = g_x16 + (size_t)b * XDIM;
    for (int i = threadIdx.x; i < XDIM; i += blockDim.x) {
        float v = (i < OBSD) ? srow[i] : act[(size_t)b * ACTD + (i - OBSD)];
        xrow[i] = __float2half_rn(v);
    }
    if (threadIdx.x == 0) {
        float best = srow[OBSD]; int bi = 0;
        for (int t = 1; t < NT; t++) { float v = srow[OBSD + t]; if (v > best) { best = v; bi = t; } }
        g_task[b] = bi;
    }
}

// wq[e,t,h] = sum_k Wk1[e,h,k] * tanh(emb[t,k]);  qb[e,t] = sum_k bk1[e,k]*tanh(emb[t,k])
__global__ void wq_kernel(const float* __restrict__ Wk1, const float* __restrict__ bk1,
                          const float* __restrict__ emb) {
    int e = blockIdx.x, t = blockIdx.y;
    __shared__ float q[DKK];
    for (int k = threadIdx.x; k < DKK; k += blockDim.x) q[k] = tanhf(emb[t * DKK + k]);
    __syncthreads();
    const float* Wb = Wk1 + (size_t)e * DH * DKK;
    for (int h = threadIdx.x; h < DH; h += blockDim.x) {
        const float* wr = Wb + (size_t)h * DKK;
        float s = 0.f;
        for (int k = 0; k < DKK; k++) s += wr[k] * q[k];
        g_wq[((size_t)e * NT + t) * DH + h] = s;
    }
    if (threadIdx.x == 0) {
        float s = 0.f;
        const float* br = bk1 + (size_t)e * DKK;
        for (int k = 0; k < DKK; k++) s += br[k] * q[k];
        g_qb[e * NT + t] = s;
    }
}

__global__ void initlogits_kernel() {
    int i = blockIdx.x * blockDim.x + threadIdx.x;
    if (i < BB * NE) {
        int b = i >> 4, e = i & 15;
        g_logits[i] = g_qb[e * NT + g_task[b]];
    }
    if (i == 0) g_loss = 0.f;
}

__global__ void softmax_kernel() {
    int b = blockIdx.x * blockDim.x + threadIdx.x;
    float l[NE];
    float mx = -1e30f;
#pragma unroll
    for (int e = 0; e < NE; e++) { l[e] = g_logits[b * NE + e]; mx = fmaxf(mx, l[e]); }
    float s = 0.f;
#pragma unroll
    for (int e = 0; e < NE; e++) { l[e] = expf(l[e] - mx); s += l[e]; }
    float inv = 1.f / s;
    float lp = 0.f;
#pragma unroll
    for (int e = 0; e < NE; e++) {
        float a = l[e] * inv;
        g_attn[b * NE + e] = a;
        float lg = logf(a + 1e-10f);
        lp += fminf(fmaxf(lg, -6.f), 0.f);
    }
#pragma unroll
    for (int o = 16; o > 0; o >>= 1) lp += __shfl_xor_sync(0xffffffffu, lp, o);
    __shared__ float red[8];
    if ((threadIdx.x & 31) == 0) red[threadIdx.x >> 5] = lp;
    __syncthreads();
    if (threadIdx.x == 0) {
        float sb = 0.f;
        for (int w = 0; w < (int)(blockDim.x >> 5); w++) sb += red[w];
        atomicAdd(&g_loss, sb);
    }
}

// tin16 = fp16( tin + sum_e attn[b,e]*bv1[e,k] )
__global__ void mixbias_kernel(const float* __restrict__ bv1) {
    int i = blockIdx.x * blockDim.x + threadIdx.x;
    if (i < BB * DKK) {
        int b = i >> 9, k = i & 511;
        float s = g_tin[i];
#pragma unroll
        for (int e = 0; e < NE; e++) s += g_attn[b * NE + e] * bv1[e * DKK + k];
        g_tin16[i] = __float2half_rn(s);
    }
}

__global__ void finalize_kernel(const float* __restrict__ Wt2, const float* __restrict__ bt2,
                                float* __restrict__ out, int out_size) {
    int wid = threadIdx.x >> 5, lane = threadIdx.x & 31;
    int b = blockIdx.x * 8 + wid;
    const float* row = g_t2 + (size_t)b * 256;
    float s = 0.f;
#pragma unroll
    for (int k = 0; k < 256; k += 32) s += row[k + lane] * Wt2[k + lane];
#pragma unroll
    for (int o = 16; o > 0; o >>= 1) s += __shfl_xor_sync(0xffffffffu, s, o);
    if (lane == 0) out[b] = s + bt2[0];
    if (blockIdx.x == 0 && threadIdx.x == 0 && out_size > BB)
        out[out_size - 1] = -(0.3f / (float)BB) * g_loss;
}

// ---------------- fp16 tensor-core GEMM (m16n8k16) ----------------
// C(M x N) = epi( A(M x K) @ B(K x N) + bias ). A fp16 row-major; B packed
// half2 [K/2][N] (k-pairs). Block 128x128x16, 8 warps (2x4), warp tile 64x32.
// EPI: 0 fp32 store, 1 relu->fp16, 2 ->fp16, 3 fused-logit, 4 relu*attn->fp16, 5 relu->fp32
#define BM 128
#define BN 128
#define BKT 16
#define AH  40    // half stride (20 words): conflict-free A-frag loads
#define BW2 136   // half2 stride: conflict-free B-frag loads (136 mod 32 = 8)

template <int EPI>
__global__ void __launch_bounds__(256) gemm_f16(
    const __half* __restrict__ A, int lda,
    const __half2* __restrict__ B, int ldb, long long sB,
    void* __restrict__ Cv, int ldc, long long sC,
    const float* __restrict__ bias, int sBias,
    int K)
{
    __shared__ __half  As[2][BM][AH];
    __shared__ __half2 Bs[2][BKT / 2][BW2];

    const int e = blockIdx.z;
    const __half2* Bp = B + (size_t)e * (size_t)sB;
    const float* biasp = bias ? bias + (size_t)e * (size_t)sBias : nullptr;
    const int bm0 = blockIdx.y * BM, bn0 = blockIdx.x * BN;
    const int tid = threadIdx.x;
    const int wid = tid >> 5, lane = tid & 31;
    const int wm = wid >> 2, wn = wid & 3;  // 2 x 4 warp grid
    const int g = lane >> 2, t = lane & 3;

    const int ar = tid >> 1, ap = tid & 1;    // A: row, 16B part (8 halves)
    const int brr = tid >> 5, bq = tid & 31;  // B: pair-row 0..7, quad (4 half2)

    const int nk = K / BKT;

    auto loadStage = [&](int s, int kt) {
        int k0 = kt * BKT;
        cpa16(&As[s][ar][ap * 8], A + (size_t)(bm0 + ar) * lda + k0 + ap * 8);
        cpa16(&Bs[s][brr][bq * 4], Bp + (size_t)(k0 / 2 + brr) * ldb + bn0 + bq * 4);
        cpa_commit();
    };

    float acc[4][4][4];
#pragma unroll
    for (int a = 0; a < 4; a++)
#pragma unroll
        for (int b2 = 0; b2 < 4; b2++)
#pragma unroll
            for (int c2 = 0; c2 < 4; c2++) acc[a][b2][c2] = 0.f;

    loadStage(0, 0);
    if (nk > 1) {
        loadStage(1, 1);
        asm volatile("cp.async.wait_group 1;\n" ::);
    } else {
        asm volatile("cp.async.wait_group 0;\n" ::);
    }
    __syncthreads();

    for (int kt = 0; kt < nk; ++kt) {
        int cur = kt & 1;
        uint32_t af[4][4], bf[4][2];
#pragma unroll
        for (int mi = 0; mi < 4; mi++) {
            int r = wm * 64 + mi * 16 + g;
            af[mi][0] = *(const uint32_t*)&As[cur][r][2 * t];
            af[mi][1] = *(const uint32_t*)&As[cur][r + 8][2 * t];
            af[mi][2] = *(const uint32_t*)&As[cur][r][2 * t + 8];
            af[mi][3] = *(const uint32_t*)&As[cur][r + 8][2 * t + 8];
        }
#pragma unroll
        for (int ni = 0; ni < 4; ni++) {
            int c = wn * 32 + ni * 8 + g;
            bf[ni][0] = *(const uint32_t*)&Bs[cur][t][c];
            bf[ni][1] = *(const uint32_t*)&Bs[cur][t + 4][c];
        }
#pragma unroll
        for (int mi = 0; mi < 4; mi++)
#pragma unroll
            for (int ni = 0; ni < 4; ni++)
                mma_f16(acc[mi][ni], af[mi], bf[ni]);

        __syncthreads();
        if (kt + 2 < nk) loadStage(cur, kt + 2);
        if (kt + 1 < nk) {
            if (kt + 2 < nk) { asm volatile("cp.async.wait_group 1;\n" ::); }
            else             { asm volatile("cp.async.wait_group 0;\n" ::); }
            __syncthreads();
        }
    }

    const int roff = bm0 + wm * 64;
    const int coff = bn0 + wn * 32;

    if (EPI == 3) {
        float rs[4][2];
#pragma unroll
        for (int mi = 0; mi < 4; mi++) { rs[mi][0] = 0.f; rs[mi][1] = 0.f; }
#pragma unroll
        for (int mi = 0; mi < 4; mi++) {
            int r0 = roff + mi * 16 + g, r1 = r0 + 8;
            const float* w0 = g_wq + ((size_t)e * NT + g_task[r0]) * DH;
            const float* w1 = g_wq + ((size_t)e * NT + g_task[r1]) * DH;
#pragma unroll
            for (int ni = 0; ni < 4; ni++) {
                int c0 = coff + ni * 8 + 2 * t;
                float b0v = biasp[c0], b1v = biasp[c0 + 1];
                rs[mi][0] += fmaxf(acc[mi][ni][0] + b0v, 0.f) * w0[c0];
                rs[mi][0] += fmaxf(acc[mi][ni][1] + b1v, 0.f) * w0[c0 + 1];
                rs[mi][1] += fmaxf(acc[mi][ni][2] + b0v, 0.f) * w1[c0];
                rs[mi][1] += fmaxf(acc[mi][ni][3] + b1v, 0.f) * w1[c0 + 1];
            }
        }
#pragma unroll
        for (int mi = 0; mi < 4; mi++)
#pragma unroll
            for (int h = 0; h < 2; h++) {
                rs[mi][h] += __shfl_xor_sync(0xffffffffu, rs[mi][h], 1);
                rs[mi][h] += __shfl_xor_sync(0xffffffffu, rs[mi][h], 2);
            }
        if (t == 0) {
#pragma unroll
            for (int mi = 0; mi < 4; mi++) {
                int r0 = roff + mi * 16 + g;
                atomicAdd(&g_logits[(size_t)r0 * NE + e], rs[mi][0]);
                atomicAdd(&g_logits[(size_t)(r0 + 8) * NE + e], rs[mi][1]);
            }
        }
    } else {
#pragma unroll
        for (int mi = 0; mi < 4; mi++) {
            int r0 = roff + mi * 16 + g, r1 = r0 + 8;
            float s0 = 1.f, s1 = 1.f;
            if (EPI == 4) { s0 = g_attn[(size_t)r0 * NE + e]; s1 = g_attn[(size_t)r1 * NE + e]; }
#pragma unroll
            for (int ni = 0; ni < 4; ni++) {
                int c0 = coff + ni * 8 + 2 * t;
                float bb0 = biasp ? biasp[c0] : 0.f;
                float bb1 = biasp ? biasp[c0 + 1] : 0.f;
                float v00 = acc[mi][ni][0] + bb0, v01 = acc[mi][ni][1] + bb1;
                float v10 = acc[mi][ni][2] + bb0, v11 = acc[mi][ni][3] + bb1;
                if (EPI == 1 || EPI == 4 || EPI == 5) {
                    v00 = fmaxf(v00, 0.f); v01 = fmaxf(v01, 0.f);
                    v10 = fmaxf(v10, 0.f); v11 = fmaxf(v11, 0.f);
                }
                if (EPI == 4) { v00 *= s0; v01 *= s0; v10 *= s1; v11 *= s1; }
                if (EPI == 1 || EPI == 2 || EPI == 4) {
                    __half* C16 = (__half*)Cv + (size_t)e * (size_t)sC;
                    *(__half2*)(C16 + (size_t)r0 * ldc + c0) = __floats2half2_rn(v00, v01);
                    *(__half2*)(C16 + (size_t)r1 * ldc + c0) = __floats2half2_rn(v10, v11);
                } else {
                    float* C32 = (float*)Cv + (size_t)e * (size_t)sC;
                    C32[(size_t)r0 * ldc + c0] = v00; C32[(size_t)r0 * ldc + c0 + 1] = v01;
                    C32[(size_t)r1 * ldc + c0] = v10; C32[(size_t)r1 * ldc + c0 + 1] = v11;
                }
            }
        }
    }
}

// ---------------- launch ----------------
extern "C" void kernel_launch(void* const* d_in, const int* in_sizes, int n_in,
                              void* d_out, int out_size) {
    const float* state = (const float*)d_in[0];
    const float* act   = (const float*)d_in[1];
    const float* repW0 = (const float*)d_in[2];
    const float* repb0 = (const float*)d_in[3];
    const float* repW1 = (const float*)d_in[4];
    const float* repb1 = (const float*)d_in[5];
    const float* emb   = (const float*)d_in[6];
    const float* Wk0   = (const float*)d_in[7];
    const float* bk0   = (const float*)d_in[8];
    const float* Wk1   = (const float*)d_in[9];
    const float* bk1   = (const float*)d_in[10];
    const float* Wv0   = (const float*)d_in[11];
    const float* bv0   = (const float*)d_in[12];
    const float* Wv1   = (const float*)d_in[13];
    const float* bv1   = (const float*)d_in[14];
    const float* Wt0   = (const float*)d_in[15];
    const float* bt0   = (const float*)d_in[16];
    const float* Wt1   = (const float*)d_in[17];
    const float* bt1   = (const float*)d_in[18];
    const float* Wt2   = (const float*)d_in[19];
    const float* bt2   = (const float*)d_in[20];
    (void)in_sizes; (void)n_in;

    __half *x16, *h016, *rep16, *gv16, *tin16, *t116;
    float *tinp, *t2p;
    __half2 *pW0, *pW1, *pWk0, *pWv0, *pWv1, *pWt0, *pWt1;
    cudaGetSymbolAddress((void**)&x16, g_x16);
    cudaGetSymbolAddress((void**)&h016, g_h016);
    cudaGetSymbolAddress((void**)&rep16, g_rep16);
    cudaGetSymbolAddress((void**)&gv16, g_gv16);
    cudaGetSymbolAddress((void**)&tin16, g_tin16);
    cudaGetSymbolAddress((void**)&t116, g_t116);
    cudaGetSymbolAddress((void**)&tinp, g_tin);
    cudaGetSymbolAddress((void**)&t2p, g_t2);
    cudaGetSymbolAddress((void**)&pW0, g_pW0);
    cudaGetSymbolAddress((void**)&pW1, g_pW1);
    cudaGetSymbolAddress((void**)&pWk0, g_pWk0);
    cudaGetSymbolAddress((void**)&pWv0, g_pWv0);
    cudaGetSymbolAddress((void**)&pWv1, g_pWv1);
    cudaGetSymbolAddress((void**)&pWt0, g_pWt0);
    cudaGetSymbolAddress((void**)&pWt1, g_pWt1);

    auto PK = [&](const float* W, __half2* P, int K, int N) {
        int total = (K / 2) * (N / 4);
        pack_kernel<<<(total + 255) / 256, 256>>>(W, P, K / 2, N);
    };
    PK(repW0, pW0, XDIM, DREP);
    PK(repW1, pW1, DREP, DREP);
    PK(Wk0, pWk0, NE * DREP, DH);     // pairs stay within experts (K even)
    PK(Wv0, pWv0, NE * DREP, DH);
    PK(Wv1, pWv1, NE * DH, DKK);
    PK(Wt0, pWt0, DKK, 512);
    PK(Wt1, pWt1, 512, 256);

    prep_kernel<<<BB, 128>>>(state, act);
    wq_kernel<<<dim3(NE, NT), 256>>>(Wk1, bk1, emb);
    initlogits_kernel<<<(BB * NE) / 256, 256>>>();

    // h0 = relu(x @ W0 + b0) -> fp16
    gemm_f16<1><<<dim3(DREP / BN, BB / BM, 1), 256>>>(
        x16, XDIM, pW0, DREP, 0, h016, DREP, 0, repb0, 0, XDIM);
    // rep = h0 @ W1 + b1 -> fp16
    gemm_f16<2><<<dim3(DREP / BN, BB / BM, 1), 256>>>(
        h016, DREP, pW1, DREP, 0, rep16, DREP, 0, repb1, 0, DREP);
    // fused logits (batched z=16)
    gemm_f16<3><<<dim3(DH / BN, BB / BM, NE), 256>>>(
        rep16, DREP, pWk0, DH, (long long)(DREP / 2) * DH, nullptr, 0, 0, bk0, DH, DREP);

    softmax_kernel<<<BB / 256, 256>>>();

    // gv = attn * relu(rep @ Wv0 + bv0) -> fp16 (batched z=16)
    gemm_f16<4><<<dim3(DH / BN, BB / BM, NE), 256>>>(
        rep16, DREP, pWv0, DH, (long long)(DREP / 2) * DH, gv16, NE * DH,
        (long long)DH, bv0, DH, DREP);
    // tower_in = gv @ Wv1_flat (K = 16384) -> fp32
    gemm_f16<0><<<dim3(DKK / BN, BB / BM, 1), 256>>>(
        gv16, NE * DH, pWv1, DKK, 0, tinp, DKK, 0, nullptr, 0, NE * DH);
    mixbias_kernel<<<(BB * DKK) / 256, 256>>>(bv1);

    // tower
    gemm_f16<1><<<dim3(512 / BN, BB / BM, 1), 256>>>(
        tin16, DKK, pWt0, 512, 0, t116, 512, 0, bt0, 0, DKK);
    gemm_f16<5><<<dim3(256 / BN, BB / BM, 1), 256>>>(
        t116, 512, pWt1, 256, 0, t2p, 256, 0, bt1, 0, 512);

    finalize_kernel<<<BB / 8, 256>>>(Wt2, bt2, (float*)d_out, out_size);
}